// round 2
// baseline (speedup 1.0000x reference)
#include <cuda_runtime.h>
#include <math.h>

// Problem constants
#define SDIM   2048
#define DIN    1024
#define NH     16
#define DH     64
#define BTOT   4
#define MROWS  (BTOT * SDIM)   // 8192
#define SCALE  0.125f          // 1/sqrt(64)

// ---------------- scratch (no cudaMalloc allowed) ----------------
__device__ float g_Q [MROWS * DIN];   // [B,S,H*D] layout (n = h*64+d)
__device__ float g_K [MROWS * DIN];
__device__ float g_V [MROWS * DIN];
__device__ float g_AO[MROWS * DIN];   // attention output, same layout

// ============================================================================
// SGEMM:  C[M,N] = A[M,K] @ B[K,N] + bias[N]
// BM=128, BN=128, BK=8, 256 threads, 8x8 micro-tile per thread.
// qkvW=1: B is the stacked per-head weight [H, K, 64]; B'[k][n] = W[n>>6][k][n&63]
// srcSel: 0 -> A_ext, 1 -> g_AO        (avoids cudaGetSymbolAddress)
// dstSel: 0 -> g_Q, 1 -> g_K, 2 -> g_V, 3 -> C_ext
// ============================================================================
__global__ __launch_bounds__(256) void sgemm_bias(
    const float* __restrict__ A_ext, const float* __restrict__ B,
    const float* __restrict__ bias, float* __restrict__ C_ext,
    int K, int N, int qkvW, int srcSel, int dstSel)
{
    __shared__ float As[8][128];   // transposed A tile
    __shared__ float Bs[8][128];

    const float* A = (srcSel == 0) ? A_ext : (const float*)g_AO;
    float* C;
    switch (dstSel) {
        case 0:  C = g_Q;  break;
        case 1:  C = g_K;  break;
        case 2:  C = g_V;  break;
        default: C = C_ext; break;
    }

    const int tid  = threadIdx.x;
    const int row0 = blockIdx.y * 128;
    const int col0 = blockIdx.x * 128;
    const int tx   = tid & 15;
    const int ty   = tid >> 4;

    const int arow = tid >> 1;           // 0..127
    const int acol = (tid & 1) << 2;     // 0 or 4
    const int brow = tid >> 5;           // 0..7
    const int bcol = (tid & 31) << 2;    // 0..124

    float acc[8][8];
#pragma unroll
    for (int i = 0; i < 8; i++)
#pragma unroll
        for (int j = 0; j < 8; j++) acc[i][j] = 0.f;

    const float* Ap = A + (size_t)(row0 + arow) * K + acol;

    const float* Bp;
    int bstride;
    if (qkvW) {
        const int n = col0 + bcol;
        const int h = n >> 6;
        const int d = n & 63;
        Bp = B + (size_t)h * K * 64 + (size_t)brow * 64 + d;
        bstride = 8 * 64;           // advance 8 k-rows inside one head block
    } else {
        Bp = B + (size_t)brow * N + col0 + bcol;
        bstride = 8 * N;
    }

    for (int k0 = 0; k0 < K; k0 += 8) {
        float4 a = *(const float4*)(Ap + k0);
        As[acol + 0][arow] = a.x;
        As[acol + 1][arow] = a.y;
        As[acol + 2][arow] = a.z;
        As[acol + 3][arow] = a.w;

        float4 b = *(const float4*)Bp;
        Bp += bstride;
        *(float4*)&Bs[brow][bcol] = b;

        __syncthreads();

#pragma unroll
        for (int kk = 0; kk < 8; kk++) {
            float4 a0 = *(const float4*)&As[kk][ty * 8];
            float4 a1 = *(const float4*)&As[kk][ty * 8 + 4];
            float4 b0 = *(const float4*)&Bs[kk][tx * 8];
            float4 b1 = *(const float4*)&Bs[kk][tx * 8 + 4];
            float ra[8] = {a0.x, a0.y, a0.z, a0.w, a1.x, a1.y, a1.z, a1.w};
            float rb[8] = {b0.x, b0.y, b0.z, b0.w, b1.x, b1.y, b1.z, b1.w};
#pragma unroll
            for (int i = 0; i < 8; i++)
#pragma unroll
                for (int j = 0; j < 8; j++)
                    acc[i][j] += ra[i] * rb[j];
        }
        __syncthreads();
    }

    const float4 bb0 = *(const float4*)(bias + col0 + tx * 8);
    const float4 bb1 = *(const float4*)(bias + col0 + tx * 8 + 4);
#pragma unroll
    for (int i = 0; i < 8; i++) {
        float* cp = C + (size_t)(row0 + ty * 8 + i) * N + col0 + tx * 8;
        float4 v0 = make_float4(acc[i][0] + bb0.x, acc[i][1] + bb0.y,
                                acc[i][2] + bb0.z, acc[i][3] + bb0.w);
        float4 v1 = make_float4(acc[i][4] + bb1.x, acc[i][5] + bb1.y,
                                acc[i][6] + bb1.z, acc[i][7] + bb1.w);
        *(float4*)cp       = v0;
        *(float4*)(cp + 4) = v1;
    }
}

// ============================================================================
// Flash attention, fp32.  One block = one (b,h) x 128-query tile.
// 256 threads; thread (rq = tid>>4, kc = tid&15) owns an 8-row x 4-col
// micro-tile of both the 128x64 score tile and the 128x64 output tile.
// Shared (dynamic, PAD=68 floats/row for 16B alignment + bank spread):
//   Qs[128][68] | Ks[64][68] | Vs[64][68] | Ps[128][68]  = 104448 B
// ============================================================================
#define BQ  128
#define BKC 64
#define PAD 68
#define ATTN_SMEM ((BQ + BKC + BKC + BQ) * PAD * 4)

__global__ __launch_bounds__(256) void attn_kernel()
{
    extern __shared__ float smem[];
    float* Qs = smem;
    float* Ks = Qs + BQ * PAD;
    float* Vs = Ks + BKC * PAD;
    float* Ps = Vs + BKC * PAD;

    const int tid = threadIdx.x;
    const int bh  = blockIdx.y;            // 0..63
    const int b   = bh >> 4;
    const int h   = bh & 15;
    const int q0  = blockIdx.x * BQ;

    const int kc = tid & 15;               // column group (k in scores, d in PV)
    const int rq = tid >> 4;               // row group: rows rq*8 .. rq*8+7

    const size_t baserow = (size_t)b * SDIM;
    const int coloff = h * DH;

    // ---- load Q tile (scale folded in) ----
    for (int v = tid; v < BQ * 16; v += 256) {
        const int r  = v >> 4;
        const int c4 = (v & 15) << 2;
        float4 q = *(const float4*)(g_Q + (baserow + q0 + r) * DIN + coloff + c4);
        float* dst = Qs + r * PAD + c4;
        dst[0] = q.x * SCALE; dst[1] = q.y * SCALE;
        dst[2] = q.z * SCALE; dst[3] = q.w * SCALE;
    }

    float m[8], l[8], O[8][4];
#pragma unroll
    for (int i = 0; i < 8; i++) {
        m[i] = -1e30f; l[i] = 0.f;
#pragma unroll
        for (int j = 0; j < 4; j++) O[i][j] = 0.f;
    }

    for (int k0 = 0; k0 < SDIM; k0 += BKC) {
        // ---- load K,V chunk ----
        for (int v = tid; v < BKC * 16; v += 256) {
            const int r  = v >> 4;
            const int c4 = (v & 15) << 2;
            const size_t g = (baserow + k0 + r) * DIN + coloff + c4;
            float4 kk = *(const float4*)(g_K + g);
            float4 vv = *(const float4*)(g_V + g);
            float* d1 = Ks + r * PAD + c4;
            float* d2 = Vs + r * PAD + c4;
            d1[0] = kk.x; d1[1] = kk.y; d1[2] = kk.z; d1[3] = kk.w;
            d2[0] = vv.x; d2[1] = vv.y; d2[2] = vv.z; d2[3] = vv.w;
        }
        __syncthreads();

        // ---- scores: s[i][j] = (Q * scale) . K   rows rq*8+i, cols kc*4+j
        float s[8][4];
#pragma unroll
        for (int i = 0; i < 8; i++)
#pragma unroll
            for (int j = 0; j < 4; j++) s[i][j] = 0.f;

#pragma unroll
        for (int d4 = 0; d4 < 16; d4++) {
            float4 kv[4];
#pragma unroll
            for (int j = 0; j < 4; j++)
                kv[j] = *(const float4*)&Ks[(kc * 4 + j) * PAD + d4 * 4];
#pragma unroll
            for (int i = 0; i < 8; i++) {
                float4 q = *(const float4*)&Qs[(rq * 8 + i) * PAD + d4 * 4];
#pragma unroll
                for (int j = 0; j < 4; j++)
                    s[i][j] += q.x * kv[j].x + q.y * kv[j].y
                             + q.z * kv[j].z + q.w * kv[j].w;
            }
        }

        // ---- online softmax (row stats shared across the 16 kc lanes) ----
#pragma unroll
        for (int i = 0; i < 8; i++) {
            float mx = s[i][0];
#pragma unroll
            for (int j = 1; j < 4; j++) mx = fmaxf(mx, s[i][j]);
#pragma unroll
            for (int w = 1; w < 16; w <<= 1)
                mx = fmaxf(mx, __shfl_xor_sync(0xffffffffu, mx, w));
            const float mnew  = fmaxf(m[i], mx);
            const float alpha = __expf(m[i] - mnew);
            m[i] = mnew;
            float rs = 0.f;
#pragma unroll
            for (int j = 0; j < 4; j++) {
                const float p = __expf(s[i][j] - mnew);
                s[i][j] = p;
                rs += p;
            }
#pragma unroll
            for (int w = 1; w < 16; w <<= 1)
                rs += __shfl_xor_sync(0xffffffffu, rs, w);
            l[i] = l[i] * alpha + rs;
#pragma unroll
            for (int j = 0; j < 4; j++) O[i][j] *= alpha;
            *(float4*)&Ps[(rq * 8 + i) * PAD + kc * 4] =
                make_float4(s[i][0], s[i][1], s[i][2], s[i][3]);
        }
        __syncthreads();

        // ---- PV: O[i][d] += P[i][k] * V[k][d],  d = kc*4+j ----
#pragma unroll
        for (int k4 = 0; k4 < 16; k4++) {
            float4 v0 = *(const float4*)&Vs[(k4 * 4 + 0) * PAD + kc * 4];
            float4 v1 = *(const float4*)&Vs[(k4 * 4 + 1) * PAD + kc * 4];
            float4 v2 = *(const float4*)&Vs[(k4 * 4 + 2) * PAD + kc * 4];
            float4 v3 = *(const float4*)&Vs[(k4 * 4 + 3) * PAD + kc * 4];
#pragma unroll
            for (int i = 0; i < 8; i++) {
                float4 p = *(const float4*)&Ps[(rq * 8 + i) * PAD + k4 * 4];
                O[i][0] += p.x * v0.x + p.y * v1.x + p.z * v2.x + p.w * v3.x;
                O[i][1] += p.x * v0.y + p.y * v1.y + p.z * v2.y + p.w * v3.y;
                O[i][2] += p.x * v0.z + p.y * v1.z + p.z * v2.z + p.w * v3.z;
                O[i][3] += p.x * v0.w + p.y * v1.w + p.z * v2.w + p.w * v3.w;
            }
        }
        __syncthreads();
    }

    // ---- normalize + write ----
#pragma unroll
    for (int i = 0; i < 8; i++) {
        const float inv = 1.f / l[i];
        float4 o = make_float4(O[i][0] * inv, O[i][1] * inv,
                               O[i][2] * inv, O[i][3] * inv);
        *(float4*)(g_AO + (baserow + q0 + rq * 8 + i) * DIN + coloff + kc * 4) = o;
    }
}

// ============================================================================
// launch
// ============================================================================
extern "C" void kernel_launch(void* const* d_in, const int* in_sizes, int n_in,
                              void* d_out, int out_size)
{
    (void)in_sizes; (void)n_in; (void)out_size;
    const float* q  = (const float*)d_in[0];
    const float* k  = (const float*)d_in[1];
    const float* v  = (const float*)d_in[2];
    const float* Wq = (const float*)d_in[3];
    const float* bq = (const float*)d_in[4];
    const float* Wk = (const float*)d_in[5];
    const float* bk = (const float*)d_in[6];
    const float* Wv = (const float*)d_in[7];
    const float* bv = (const float*)d_in[8];
    const float* Wo = (const float*)d_in[9];
    const float* bo = (const float*)d_in[10];
    float* out = (float*)d_out;

    cudaFuncSetAttribute(attn_kernel,
                         cudaFuncAttributeMaxDynamicSharedMemorySize, ATTN_SMEM);

    dim3 gg(DIN / 128, MROWS / 128);   // (8, 64)

    // QKV projections -> g_Q / g_K / g_V (device globals, selected in-kernel)
    sgemm_bias<<<gg, 256>>>(q, Wq, bq, nullptr, DIN, DIN, 1, 0, 0);
    sgemm_bias<<<gg, 256>>>(k, Wk, bk, nullptr, DIN, DIN, 1, 0, 1);
    sgemm_bias<<<gg, 256>>>(v, Wv, bv, nullptr, DIN, DIN, 1, 0, 2);

    attn_kernel<<<dim3(SDIM / BQ, BTOT * NH), 256, ATTN_SMEM>>>();

    // output projection: A = g_AO (srcSel=1), C = d_out
    sgemm_bias<<<gg, 256>>>(nullptr, Wo, bo, out, DIN, DIN, 0, 1, 3);
}

// round 5
// speedup vs baseline: 1.6476x; 1.6476x over previous
#include <cuda_runtime.h>
#include <math.h>

// Problem constants
#define SDIM   2048
#define DIN    1024
#define NH     16
#define DH     64
#define BTOT   4
#define MROWS  (BTOT * SDIM)   // 8192
#define SCALE  0.125f          // 1/sqrt(64)

// ---------------- scratch (no cudaMalloc allowed) ----------------
__device__ float g_Q [MROWS * DIN];   // [B,S,H*D] layout (n = h*64+d)
__device__ float g_K [MROWS * DIN];
__device__ float g_V [MROWS * DIN];
__device__ float g_AO[MROWS * DIN];

// ---------------- tf32 helpers ----------------
__device__ __forceinline__ unsigned f2tf(float f) {
    unsigned u;
    asm("cvt.rna.tf32.f32 %0, %1;" : "=r"(u) : "f"(f));
    return u;
}
// split x into hi (tf32) and lo (tf32 of residual)
__device__ __forceinline__ void tfsplit(float x, unsigned& hi, unsigned& lo) {
    hi = f2tf(x);
    lo = f2tf(x - __uint_as_float(hi));
}

// D(16x8) += A(16x8) * B(8x8), tf32 inputs, fp32 accum
__device__ __forceinline__ void mma8(float* c,
    unsigned a0, unsigned a1, unsigned a2, unsigned a3,
    unsigned b0, unsigned b1)
{
    asm volatile(
        "mma.sync.aligned.m16n8k8.row.col.f32.tf32.tf32.f32 "
        "{%0,%1,%2,%3}, {%4,%5,%6,%7}, {%8,%9}, {%0,%1,%2,%3};"
        : "+f"(c[0]), "+f"(c[1]), "+f"(c[2]), "+f"(c[3])
        : "r"(a0), "r"(a1), "r"(a2), "r"(a3), "r"(b0), "r"(b1));
}

// ============================================================================
// split-tf32 GEMM: C[M,N] = A[M,K] @ B[K,N] + bias[N];  M=8192, N=K=1024
// Block 128x128, BK=32, 256 threads = 8 warps (2x4), warp tile 64x32.
// terms=3:  AH*BH + AH*BL + AL*BH   (near-fp32)
// terms=2:  AH*BH + AL*BH           (A exact, B rounded once)
// smem (dynamic): AsH/AsL[128][36], BsH/BsL[32][136] = 71680 B
// qkvW=1: B is stacked per-head weight [H, K, 64]
// srcSel: 0 -> A_ext, 1 -> g_AO;  dstSel: 0 g_Q, 1 g_K, 2 g_V, 3 C_ext
// ============================================================================
#define APAD 36
#define BPAD 136
#define GSMEM ((128 * APAD * 2 + 32 * BPAD * 2) * 4)

__global__ __launch_bounds__(256, 2) void gemm_split(
    const float* __restrict__ A_ext, const float* __restrict__ B,
    const float* __restrict__ bias, float* __restrict__ C_ext,
    int qkvW, int srcSel, int dstSel, int terms)
{
    const int K = DIN, N = DIN;
    extern __shared__ unsigned gsm[];
    unsigned* AsH = gsm;
    unsigned* AsL = AsH + 128 * APAD;
    unsigned* BsH = AsL + 128 * APAD;
    unsigned* BsL = BsH + 32 * BPAD;

    const float* A = srcSel ? (const float*)g_AO : A_ext;
    float* C;
    switch (dstSel) {
        case 0:  C = g_Q;  break;
        case 1:  C = g_K;  break;
        case 2:  C = g_V;  break;
        default: C = C_ext; break;
    }

    const int tid  = threadIdx.x;
    const int warp = tid >> 5;
    const int lane = tid & 31;
    const int grp  = lane >> 2;     // 0..7
    const int tig  = lane & 3;      // 0..3
    const int row0 = blockIdx.y * 128;
    const int col0 = blockIdx.x * 128;
    const int wm   = (warp >> 2) * 64;
    const int wn   = (warp & 3) * 32;
    const bool t3  = (terms == 3);

    float acc[4][4][4];
#pragma unroll
    for (int mf = 0; mf < 4; mf++)
#pragma unroll
        for (int nf = 0; nf < 4; nf++)
#pragma unroll
            for (int i = 0; i < 4; i++) acc[mf][nf][i] = 0.f;

    for (int k0 = 0; k0 < K; k0 += 32) {
        __syncthreads();
        // ---- load A tile 128x32, split ----
#pragma unroll
        for (int i = 0; i < 4; i++) {
            int idx = tid + i * 256;
            int r   = idx >> 3;
            int k4  = (idx & 7) << 2;
            float4 a = *(const float4*)(A + (size_t)(row0 + r) * K + k0 + k4);
            unsigned h, l;
            tfsplit(a.x, h, l); AsH[r * APAD + k4 + 0] = h; AsL[r * APAD + k4 + 0] = l;
            tfsplit(a.y, h, l); AsH[r * APAD + k4 + 1] = h; AsL[r * APAD + k4 + 1] = l;
            tfsplit(a.z, h, l); AsH[r * APAD + k4 + 2] = h; AsL[r * APAD + k4 + 2] = l;
            tfsplit(a.w, h, l); AsH[r * APAD + k4 + 3] = h; AsL[r * APAD + k4 + 3] = l;
        }
        // ---- load B tile 32x128 ----
#pragma unroll
        for (int i = 0; i < 4; i++) {
            int idx = tid + i * 256;
            int kr  = idx >> 5;
            int n4  = (idx & 31) << 2;
            const float* bp;
            if (qkvW) {
                int n = col0 + n4;
                bp = B + (size_t)(n >> 6) * K * 64 + (size_t)(k0 + kr) * 64 + (n & 63);
            } else {
                bp = B + (size_t)(k0 + kr) * N + col0 + n4;
            }
            float4 b = *(const float4*)bp;
            if (t3) {
                unsigned h, l;
                tfsplit(b.x, h, l); BsH[kr * BPAD + n4 + 0] = h; BsL[kr * BPAD + n4 + 0] = l;
                tfsplit(b.y, h, l); BsH[kr * BPAD + n4 + 1] = h; BsL[kr * BPAD + n4 + 1] = l;
                tfsplit(b.z, h, l); BsH[kr * BPAD + n4 + 2] = h; BsL[kr * BPAD + n4 + 2] = l;
                tfsplit(b.w, h, l); BsH[kr * BPAD + n4 + 3] = h; BsL[kr * BPAD + n4 + 3] = l;
            } else {
                BsH[kr * BPAD + n4 + 0] = f2tf(b.x);
                BsH[kr * BPAD + n4 + 1] = f2tf(b.y);
                BsH[kr * BPAD + n4 + 2] = f2tf(b.z);
                BsH[kr * BPAD + n4 + 3] = f2tf(b.w);
            }
        }
        __syncthreads();

#pragma unroll
        for (int ks = 0; ks < 4; ks++) {
            const int kb = ks * 8;
            unsigned aH[4][4], aL[4][4];
#pragma unroll
            for (int mf = 0; mf < 4; mf++) {
                int m0 = (wm + mf * 16 + grp) * APAD;
                int m1 = m0 + 8 * APAD;
                aH[mf][0] = AsH[m0 + kb + tig];
                aH[mf][1] = AsH[m1 + kb + tig];
                aH[mf][2] = AsH[m0 + kb + tig + 4];
                aH[mf][3] = AsH[m1 + kb + tig + 4];
                aL[mf][0] = AsL[m0 + kb + tig];
                aL[mf][1] = AsL[m1 + kb + tig];
                aL[mf][2] = AsL[m0 + kb + tig + 4];
                aL[mf][3] = AsL[m1 + kb + tig + 4];
            }
#pragma unroll
            for (int nf = 0; nf < 4; nf++) {
                int n = wn + nf * 8 + grp;
                unsigned bH0 = BsH[(kb + tig    ) * BPAD + n];
                unsigned bH1 = BsH[(kb + tig + 4) * BPAD + n];
#pragma unroll
                for (int mf = 0; mf < 4; mf++)
                    mma8(acc[mf][nf], aH[mf][0], aH[mf][1], aH[mf][2], aH[mf][3], bH0, bH1);
#pragma unroll
                for (int mf = 0; mf < 4; mf++)
                    mma8(acc[mf][nf], aL[mf][0], aL[mf][1], aL[mf][2], aL[mf][3], bH0, bH1);
                if (t3) {
                    unsigned bL0 = BsL[(kb + tig    ) * BPAD + n];
                    unsigned bL1 = BsL[(kb + tig + 4) * BPAD + n];
#pragma unroll
                    for (int mf = 0; mf < 4; mf++)
                        mma8(acc[mf][nf], aH[mf][0], aH[mf][1], aH[mf][2], aH[mf][3], bL0, bL1);
                }
            }
        }
    }

    // ---- epilogue: bias + store ----
#pragma unroll
    for (int nf = 0; nf < 4; nf++) {
        int c = col0 + wn + nf * 8 + 2 * tig;
        float bv0 = bias[c], bv1 = bias[c + 1];
#pragma unroll
        for (int mf = 0; mf < 4; mf++) {
            int r = row0 + wm + mf * 16 + grp;
            float2 v0 = make_float2(acc[mf][nf][0] + bv0, acc[mf][nf][1] + bv1);
            float2 v1 = make_float2(acc[mf][nf][2] + bv0, acc[mf][nf][3] + bv1);
            *(float2*)(C + (size_t)r * N + c)       = v0;
            *(float2*)(C + (size_t)(r + 8) * N + c) = v1;
        }
    }
}

// ============================================================================
// split-tf32 flash attention. Block = (b,h) x 128-query tile, 256 thr, 8 warps.
// QK: 3-term (Q,K split).  PV: 2-term (P single tf32, V split).
// smem (dynamic): QsH/QsL[128][68], KsH/KsL[64][68], VsH/VsL[64][72], Ps[128][68]
//   = 176128 B  -> 1 block/SM
// ============================================================================
#define QPAD 68
#define KPAD 68
#define VPAD 72
#define ATTN_SMEM ((128 * QPAD * 2 + 64 * KPAD * 2 + 64 * VPAD * 2 + 128 * QPAD) * 4)

__global__ __launch_bounds__(256) void attn_split()
{
    extern __shared__ unsigned sm[];
    unsigned* QsH = sm;
    unsigned* QsL = QsH + 128 * QPAD;
    unsigned* KsH = QsL + 128 * QPAD;
    unsigned* KsL = KsH + 64 * KPAD;
    unsigned* VsH = KsL + 64 * KPAD;
    unsigned* VsL = VsH + 64 * VPAD;
    unsigned* Ps  = VsL + 64 * VPAD;

    const int tid  = threadIdx.x;
    const int warp = tid >> 5;
    const int lane = tid & 31;
    const int grp  = lane >> 2;
    const int tig  = lane & 3;

    const int bh = blockIdx.y;
    const int b  = bh >> 4;
    const int h  = bh & 15;
    const int q0 = blockIdx.x * 128;
    const size_t base = (size_t)b * SDIM;
    const int coff = h * DH;
    const int qw   = warp * 16;

    // ---- load Q tile (scale folded; SCALE is a power of 2 so split is exact) ----
    for (int i = tid; i < 128 * 16; i += 256) {
        int r  = i >> 4;
        int c4 = (i & 15) << 2;
        float4 q = *(const float4*)(g_Q + (base + q0 + r) * DIN + coff + c4);
        unsigned hh, ll;
        unsigned* dh = QsH + r * QPAD + c4;
        unsigned* dl = QsL + r * QPAD + c4;
        tfsplit(q.x * SCALE, hh, ll); dh[0] = hh; dl[0] = ll;
        tfsplit(q.y * SCALE, hh, ll); dh[1] = hh; dl[1] = ll;
        tfsplit(q.z * SCALE, hh, ll); dh[2] = hh; dl[2] = ll;
        tfsplit(q.w * SCALE, hh, ll); dh[3] = hh; dl[3] = ll;
    }

    float m0 = -1e30f, m1 = -1e30f, l0 = 0.f, l1 = 0.f;
    float O[8][4];
#pragma unroll
    for (int nf = 0; nf < 8; nf++)
#pragma unroll
        for (int i = 0; i < 4; i++) O[nf][i] = 0.f;

    for (int kk = 0; kk < SDIM; kk += 64) {
        __syncthreads();
        // ---- load K,V chunk 64x64 (split) ----
        for (int i = tid; i < 64 * 16; i += 256) {
            int r  = i >> 4;
            int c4 = (i & 15) << 2;
            size_t g = (base + kk + r) * DIN + coff + c4;
            float4 kv = *(const float4*)(g_K + g);
            float4 vv = *(const float4*)(g_V + g);
            unsigned hh, ll;
            unsigned* kh = KsH + r * KPAD + c4;
            unsigned* kl = KsL + r * KPAD + c4;
            unsigned* vh = VsH + r * VPAD + c4;
            unsigned* vl = VsL + r * VPAD + c4;
            tfsplit(kv.x, hh, ll); kh[0] = hh; kl[0] = ll;
            tfsplit(kv.y, hh, ll); kh[1] = hh; kl[1] = ll;
            tfsplit(kv.z, hh, ll); kh[2] = hh; kl[2] = ll;
            tfsplit(kv.w, hh, ll); kh[3] = hh; kl[3] = ll;
            tfsplit(vv.x, hh, ll); vh[0] = hh; vl[0] = ll;
            tfsplit(vv.y, hh, ll); vh[1] = hh; vl[1] = ll;
            tfsplit(vv.z, hh, ll); vh[2] = hh; vl[2] = ll;
            tfsplit(vv.w, hh, ll); vh[3] = hh; vl[3] = ll;
        }
        __syncthreads();

        // ---- S(16x64) = Q . K^T, 3-term ----
        float S[8][4];
#pragma unroll
        for (int nf = 0; nf < 8; nf++)
#pragma unroll
            for (int i = 0; i < 4; i++) S[nf][i] = 0.f;

#pragma unroll
        for (int ks = 0; ks < 8; ks++) {
            const int kb = ks * 8;
            const int r0 = (qw + grp) * QPAD;
            const int r1 = r0 + 8 * QPAD;
            unsigned aH0 = QsH[r0 + kb + tig],     aH1 = QsH[r1 + kb + tig];
            unsigned aH2 = QsH[r0 + kb + tig + 4], aH3 = QsH[r1 + kb + tig + 4];
            unsigned aL0 = QsL[r0 + kb + tig],     aL1 = QsL[r1 + kb + tig];
            unsigned aL2 = QsL[r0 + kb + tig + 4], aL3 = QsL[r1 + kb + tig + 4];
#pragma unroll
            for (int nf = 0; nf < 8; nf++) {
                const int kr = (nf * 8 + grp) * KPAD;
                unsigned bH0 = KsH[kr + kb + tig];
                unsigned bH1 = KsH[kr + kb + tig + 4];
                unsigned bL0 = KsL[kr + kb + tig];
                unsigned bL1 = KsL[kr + kb + tig + 4];
                mma8(S[nf], aH0, aH1, aH2, aH3, bH0, bH1);
                mma8(S[nf], aH0, aH1, aH2, aH3, bL0, bL1);
                mma8(S[nf], aL0, aL1, aL2, aL3, bH0, bH1);
            }
        }

        // ---- online softmax ----
        float mx0 = -1e30f, mx1 = -1e30f;
#pragma unroll
        for (int nf = 0; nf < 8; nf++) {
            mx0 = fmaxf(mx0, fmaxf(S[nf][0], S[nf][1]));
            mx1 = fmaxf(mx1, fmaxf(S[nf][2], S[nf][3]));
        }
        mx0 = fmaxf(mx0, __shfl_xor_sync(0xffffffffu, mx0, 1));
        mx0 = fmaxf(mx0, __shfl_xor_sync(0xffffffffu, mx0, 2));
        mx1 = fmaxf(mx1, __shfl_xor_sync(0xffffffffu, mx1, 1));
        mx1 = fmaxf(mx1, __shfl_xor_sync(0xffffffffu, mx1, 2));

        const float mn0 = fmaxf(m0, mx0);
        const float mn1 = fmaxf(m1, mx1);
        const float al0 = __expf(m0 - mn0);
        const float al1 = __expf(m1 - mn1);
        m0 = mn0; m1 = mn1;

        float rs0 = 0.f, rs1 = 0.f;
#pragma unroll
        for (int nf = 0; nf < 8; nf++) {
            float p0 = __expf(S[nf][0] - mn0);
            float p1 = __expf(S[nf][1] - mn0);
            float p2 = __expf(S[nf][2] - mn1);
            float p3 = __expf(S[nf][3] - mn1);
            rs0 += p0 + p1;
            rs1 += p2 + p3;
            const int cb = nf * 8 + 2 * tig;
            *(uint2*)&Ps[(qw + grp    ) * QPAD + cb] = make_uint2(f2tf(p0), f2tf(p1));
            *(uint2*)&Ps[(qw + grp + 8) * QPAD + cb] = make_uint2(f2tf(p2), f2tf(p3));
        }
        rs0 += __shfl_xor_sync(0xffffffffu, rs0, 1);
        rs0 += __shfl_xor_sync(0xffffffffu, rs0, 2);
        rs1 += __shfl_xor_sync(0xffffffffu, rs1, 1);
        rs1 += __shfl_xor_sync(0xffffffffu, rs1, 2);
        l0 = l0 * al0 + rs0;
        l1 = l1 * al1 + rs1;

#pragma unroll
        for (int nf = 0; nf < 8; nf++) {
            O[nf][0] *= al0; O[nf][1] *= al0;
            O[nf][2] *= al1; O[nf][3] *= al1;
        }
        __syncwarp();

        // ---- O += P . V, 2-term (V split) ----
#pragma unroll
        for (int ks = 0; ks < 8; ks++) {
            const int kb = ks * 8;
            const int r0 = (qw + grp) * QPAD;
            const int r1 = r0 + 8 * QPAD;
            unsigned a0 = Ps[r0 + kb + tig],     a1 = Ps[r1 + kb + tig];
            unsigned a2 = Ps[r0 + kb + tig + 4], a3 = Ps[r1 + kb + tig + 4];
#pragma unroll
            for (int nf = 0; nf < 8; nf++) {
                const int v0r = (kb + tig) * VPAD + nf * 8 + grp;
                const int v1r = (kb + tig + 4) * VPAD + nf * 8 + grp;
                unsigned bH0 = VsH[v0r], bH1 = VsH[v1r];
                unsigned bL0 = VsL[v0r], bL1 = VsL[v1r];
                mma8(O[nf], a0, a1, a2, a3, bH0, bH1);
                mma8(O[nf], a0, a1, a2, a3, bL0, bL1);
            }
        }
    }

    // ---- normalize + write ----
    const float inv0 = 1.f / l0;
    const float inv1 = 1.f / l1;
#pragma unroll
    for (int nf = 0; nf < 8; nf++) {
        const int c = coff + nf * 8 + 2 * tig;
        const size_t r0g = base + q0 + qw + grp;
        float2 o0 = make_float2(O[nf][0] * inv0, O[nf][1] * inv0);
        float2 o1 = make_float2(O[nf][2] * inv1, O[nf][3] * inv1);
        *(float2*)(g_AO + r0g * DIN + c)       = o0;
        *(float2*)(g_AO + (r0g + 8) * DIN + c) = o1;
    }
}

// ============================================================================
// launch
// ============================================================================
extern "C" void kernel_launch(void* const* d_in, const int* in_sizes, int n_in,
                              void* d_out, int out_size)
{
    (void)in_sizes; (void)n_in; (void)out_size;
    const float* q  = (const float*)d_in[0];
    const float* k  = (const float*)d_in[1];
    const float* v  = (const float*)d_in[2];
    const float* Wq = (const float*)d_in[3];
    const float* bq = (const float*)d_in[4];
    const float* Wk = (const float*)d_in[5];
    const float* bk = (const float*)d_in[6];
    const float* Wv = (const float*)d_in[7];
    const float* bv = (const float*)d_in[8];
    const float* Wo = (const float*)d_in[9];
    const float* bo = (const float*)d_in[10];
    float* out = (float*)d_out;

    cudaFuncSetAttribute(gemm_split,
                         cudaFuncAttributeMaxDynamicSharedMemorySize, GSMEM);
    cudaFuncSetAttribute(attn_split,
                         cudaFuncAttributeMaxDynamicSharedMemorySize, ATTN_SMEM);

    dim3 gg(DIN / 128, MROWS / 128);   // (8, 64)

    // Q,K projections: 3-term (feeds the softmax-amplified path)
    gemm_split<<<gg, 256, GSMEM>>>(q, Wq, bq, nullptr, 1, 0, 0, 3);
    gemm_split<<<gg, 256, GSMEM>>>(k, Wk, bk, nullptr, 1, 0, 1, 3);
    // V projection: 2-term (linear path)
    gemm_split<<<gg, 256, GSMEM>>>(v, Wv, bv, nullptr, 1, 0, 2, 2);

    attn_split<<<dim3(SDIM / 128, BTOT * NH), 256, ATTN_SMEM>>>();

    // output projection: 2-term
    gemm_split<<<gg, 256, GSMEM>>>(nullptr, Wo, bo, out, 0, 1, 3, 2);
}

// round 6
// speedup vs baseline: 3.1844x; 1.9328x over previous
#include <cuda_runtime.h>
#include <math.h>

// Problem constants
#define SDIM   2048
#define DIN    1024
#define NH     16
#define DH     64
#define BTOT   4
#define MROWS  (BTOT * SDIM)   // 8192
#define SCALE  0.125f          // 1/sqrt(64)

// ---------------- scratch (no cudaMalloc allowed) ----------------
__device__ float g_Q [MROWS * DIN];   // [B,S,H*D] layout (n = h*64+d)
__device__ float g_K [MROWS * DIN];
__device__ float g_V [MROWS * DIN];
__device__ float g_AO[MROWS * DIN];

// ---------------- precision helpers ----------------
__device__ __forceinline__ unsigned f2tf(float f) {
    unsigned u;
    asm("cvt.rna.tf32.f32 %0, %1;" : "=r"(u) : "f"(f));
    return u;
}
// pack two floats as bf16x2: e0 -> low half (even k), e1 -> high half (odd k)
__device__ __forceinline__ unsigned bfpack(float e0, float e1) {
    unsigned u;
    asm("cvt.rn.bf16x2.f32 %0, %1, %2;" : "=r"(u) : "f"(e1), "f"(e0));
    return u;
}
// split (e0,e1) into hi bf16x2 and lo (residual) bf16x2
__device__ __forceinline__ void bfsplit2(float e0, float e1, unsigned& hi, unsigned& lo) {
    hi = bfpack(e0, e1);
    float h0 = __uint_as_float((hi & 0x0000ffffu) << 16);
    float h1 = __uint_as_float(hi & 0xffff0000u);
    lo = bfpack(e0 - h0, e1 - h1);
}

// D(16x8) += A(16x8) * B(8x8), tf32, fp32 accum
__device__ __forceinline__ void mma8(float* c,
    unsigned a0, unsigned a1, unsigned a2, unsigned a3,
    unsigned b0, unsigned b1)
{
    asm volatile(
        "mma.sync.aligned.m16n8k8.row.col.f32.tf32.tf32.f32 "
        "{%0,%1,%2,%3}, {%4,%5,%6,%7}, {%8,%9}, {%0,%1,%2,%3};"
        : "+f"(c[0]), "+f"(c[1]), "+f"(c[2]), "+f"(c[3])
        : "r"(a0), "r"(a1), "r"(a2), "r"(a3), "r"(b0), "r"(b1));
}
// D(16x8) += A(16x16) * B(16x8), bf16, fp32 accum
__device__ __forceinline__ void mma16(float* c,
    unsigned a0, unsigned a1, unsigned a2, unsigned a3,
    unsigned b0, unsigned b1)
{
    asm volatile(
        "mma.sync.aligned.m16n8k16.row.col.f32.bf16.bf16.f32 "
        "{%0,%1,%2,%3}, {%4,%5,%6,%7}, {%8,%9}, {%0,%1,%2,%3};"
        : "+f"(c[0]), "+f"(c[1]), "+f"(c[2]), "+f"(c[3])
        : "r"(a0), "r"(a1), "r"(a2), "r"(a3), "r"(b0), "r"(b1));
}

// ============================================================================
// split-bf16 GEMM (3-term 3xBF16 ~ fp32): C = A[M,K] @ B[K,N] + bias
// Block 128x128, BK=32, 256 threads = 8 warps (2x4), warp tile 64x32.
// A smem: [m][kpair] bf16x2, pad 20 (20%8==4 -> A-frag conflict-free)
// B smem: [kpair][n] bf16x2, pad 136 (136%32==8 -> B-frag conflict-free)
// qkvW=1: B is stacked per-head weight [H, K, 64]
// srcSel: 0 -> A_ext, 1 -> g_AO;  dstSel: 0 g_Q, 1 g_K, 2 g_V, 3 C_ext
// ============================================================================
#define GAPAD 20
#define GBPAD 136
#define GSMEM ((128 * GAPAD * 2 + 16 * GBPAD * 2) * 4)   // 37888 B

__global__ __launch_bounds__(256, 2) void gemm_bf16(
    const float* __restrict__ A_ext, const float* __restrict__ B,
    const float* __restrict__ bias, float* __restrict__ C_ext,
    int qkvW, int srcSel, int dstSel)
{
    const int K = DIN, N = DIN;
    extern __shared__ unsigned gsm[];
    unsigned* AsH = gsm;                    // [128][GAPAD]
    unsigned* AsL = AsH + 128 * GAPAD;
    unsigned* BsH = AsL + 128 * GAPAD;      // [16][GBPAD]
    unsigned* BsL = BsH + 16 * GBPAD;

    const float* A = srcSel ? (const float*)g_AO : A_ext;
    float* C;
    switch (dstSel) {
        case 0:  C = g_Q;  break;
        case 1:  C = g_K;  break;
        case 2:  C = g_V;  break;
        default: C = C_ext; break;
    }

    const int tid  = threadIdx.x;
    const int warp = tid >> 5;
    const int lane = tid & 31;
    const int grp  = lane >> 2;     // 0..7
    const int tig  = lane & 3;      // 0..3
    const int row0 = blockIdx.y * 128;
    const int col0 = blockIdx.x * 128;
    const int wm   = (warp >> 2) * 64;
    const int wn   = (warp & 3) * 32;

    float acc[4][4][4];
#pragma unroll
    for (int mf = 0; mf < 4; mf++)
#pragma unroll
        for (int nf = 0; nf < 4; nf++)
#pragma unroll
            for (int i = 0; i < 4; i++) acc[mf][nf][i] = 0.f;

    for (int k0 = 0; k0 < K; k0 += 32) {
        __syncthreads();
        // ---- A tile 128x32 -> [m][kpair] hi/lo ----
#pragma unroll
        for (int i = 0; i < 4; i++) {
            int idx = tid + i * 256;
            int r   = idx >> 3;
            int k4  = (idx & 7) << 2;
            float4 a = *(const float4*)(A + (size_t)(row0 + r) * K + k0 + k4);
            unsigned h0, l0, h1, l1;
            bfsplit2(a.x, a.y, h0, l0);
            bfsplit2(a.z, a.w, h1, l1);
            *(uint2*)&AsH[r * GAPAD + (k4 >> 1)] = make_uint2(h0, h1);
            *(uint2*)&AsL[r * GAPAD + (k4 >> 1)] = make_uint2(l0, l1);
        }
        // ---- B tile 32x128 -> [kpair][n] hi/lo (pair spans 2 global k-rows) ----
#pragma unroll
        for (int i = 0; i < 4; i++) {
            int idx = tid + i * 256;
            int kp  = idx >> 6;              // 0..15
            int n2  = (idx & 63) << 1;       // 0..126 step 2
            int k   = k0 + kp * 2;
            const float *b0p, *b1p;
            if (qkvW) {
                int n = col0 + n2;
                b0p = B + (size_t)(n >> 6) * K * 64 + (size_t)k * 64 + (n & 63);
                b1p = b0p + 64;
            } else {
                b0p = B + (size_t)k * N + col0 + n2;
                b1p = b0p + N;
            }
            float2 r0 = *(const float2*)b0p;   // row k:   cols n2, n2+1
            float2 r1 = *(const float2*)b1p;   // row k+1
            unsigned h0, l0, h1, l1;
            bfsplit2(r0.x, r1.x, h0, l0);      // pair (k,k+1) at col n2
            bfsplit2(r0.y, r1.y, h1, l1);      // at col n2+1
            *(uint2*)&BsH[kp * GBPAD + n2] = make_uint2(h0, h1);
            *(uint2*)&BsL[kp * GBPAD + n2] = make_uint2(l0, l1);
        }
        __syncthreads();

        // ---- 2 ksteps of m16n8k16, 3-term ----
#pragma unroll
        for (int s = 0; s < 2; s++) {
            const int kb = s * 8;    // kpair base
            unsigned aH[4][4], aL[4][4];
#pragma unroll
            for (int mf = 0; mf < 4; mf++) {
                int m0 = (wm + mf * 16 + grp) * GAPAD;
                int m1 = m0 + 8 * GAPAD;
                aH[mf][0] = AsH[m0 + kb + tig];
                aH[mf][1] = AsH[m1 + kb + tig];
                aH[mf][2] = AsH[m0 + kb + tig + 4];
                aH[mf][3] = AsH[m1 + kb + tig + 4];
                aL[mf][0] = AsL[m0 + kb + tig];
                aL[mf][1] = AsL[m1 + kb + tig];
                aL[mf][2] = AsL[m0 + kb + tig + 4];
                aL[mf][3] = AsL[m1 + kb + tig + 4];
            }
#pragma unroll
            for (int nf = 0; nf < 4; nf++) {
                int n = wn + nf * 8 + grp;
                unsigned bH0 = BsH[(kb + tig    ) * GBPAD + n];
                unsigned bH1 = BsH[(kb + tig + 4) * GBPAD + n];
                unsigned bL0 = BsL[(kb + tig    ) * GBPAD + n];
                unsigned bL1 = BsL[(kb + tig + 4) * GBPAD + n];
#pragma unroll
                for (int mf = 0; mf < 4; mf++)
                    mma16(acc[mf][nf], aH[mf][0], aH[mf][1], aH[mf][2], aH[mf][3], bH0, bH1);
#pragma unroll
                for (int mf = 0; mf < 4; mf++)
                    mma16(acc[mf][nf], aH[mf][0], aH[mf][1], aH[mf][2], aH[mf][3], bL0, bL1);
#pragma unroll
                for (int mf = 0; mf < 4; mf++)
                    mma16(acc[mf][nf], aL[mf][0], aL[mf][1], aL[mf][2], aL[mf][3], bH0, bH1);
            }
        }
    }

    // ---- epilogue: bias + store ----
#pragma unroll
    for (int nf = 0; nf < 4; nf++) {
        int c = col0 + wn + nf * 8 + 2 * tig;
        float bv0 = bias[c], bv1 = bias[c + 1];
#pragma unroll
        for (int mf = 0; mf < 4; mf++) {
            int r = row0 + wm + mf * 16 + grp;
            float2 v0 = make_float2(acc[mf][nf][0] + bv0, acc[mf][nf][1] + bv1);
            float2 v1 = make_float2(acc[mf][nf][2] + bv0, acc[mf][nf][3] + bv1);
            *(float2*)(C + (size_t)r * N + c)       = v0;
            *(float2*)(C + (size_t)(r + 8) * N + c) = v1;
        }
    }
}

// ============================================================================
// Flash attention: QK = split-bf16 3-term; PV = single tf32.
// Block = (b,h) x 128-query tile, 256 thr, 8 warps; warp owns 16 q-rows.
// smem: QsH/L [128][36] pairs, KsH/L [64][36] pairs, Vs [64][72] tf32,
//       Ps [128][68] tf32  = 108544 B  -> 2 blocks/SM
// ============================================================================
#define AQPAD 36
#define AKPAD 36
#define AVPAD 72
#define APPAD 68
#define ATTN_SMEM ((128 * AQPAD * 2 + 64 * AKPAD * 2 + 64 * AVPAD + 128 * APPAD) * 4)

__global__ __launch_bounds__(256, 2) void attn_bf16()
{
    extern __shared__ unsigned sm[];
    unsigned* QsH = sm;
    unsigned* QsL = QsH + 128 * AQPAD;
    unsigned* KsH = QsL + 128 * AQPAD;
    unsigned* KsL = KsH + 64 * AKPAD;
    unsigned* Vs  = KsL + 64 * AKPAD;
    unsigned* Ps  = Vs  + 64 * AVPAD;

    const int tid  = threadIdx.x;
    const int warp = tid >> 5;
    const int lane = tid & 31;
    const int grp  = lane >> 2;
    const int tig  = lane & 3;

    const int bh = blockIdx.y;
    const int b  = bh >> 4;
    const int h  = bh & 15;
    const int q0 = blockIdx.x * 128;
    const size_t base = (size_t)b * SDIM;
    const int coff = h * DH;
    const int qw   = warp * 16;

    // ---- load Q tile (scale folded), split-bf16 pairs ----
    for (int i = tid; i < 128 * 16; i += 256) {
        int r  = i >> 4;
        int c4 = (i & 15) << 2;
        float4 q = *(const float4*)(g_Q + (base + q0 + r) * DIN + coff + c4);
        unsigned h0, l0, h1, l1;
        bfsplit2(q.x * SCALE, q.y * SCALE, h0, l0);
        bfsplit2(q.z * SCALE, q.w * SCALE, h1, l1);
        *(uint2*)&QsH[r * AQPAD + (c4 >> 1)] = make_uint2(h0, h1);
        *(uint2*)&QsL[r * AQPAD + (c4 >> 1)] = make_uint2(l0, l1);
    }

    float m0 = -1e30f, m1 = -1e30f, l0s = 0.f, l1s = 0.f;
    float O[8][4];
#pragma unroll
    for (int nf = 0; nf < 8; nf++)
#pragma unroll
        for (int i = 0; i < 4; i++) O[nf][i] = 0.f;

    for (int kk = 0; kk < SDIM; kk += 64) {
        __syncthreads();
        // ---- load K (split-bf16 pairs) and V (tf32) chunk 64x64 ----
        for (int i = tid; i < 64 * 16; i += 256) {
            int r  = i >> 4;
            int c4 = (i & 15) << 2;
            size_t g = (base + kk + r) * DIN + coff + c4;
            float4 kv = *(const float4*)(g_K + g);
            float4 vv = *(const float4*)(g_V + g);
            unsigned h0, l0, h1, l1;
            bfsplit2(kv.x, kv.y, h0, l0);
            bfsplit2(kv.z, kv.w, h1, l1);
            *(uint2*)&KsH[r * AKPAD + (c4 >> 1)] = make_uint2(h0, h1);
            *(uint2*)&KsL[r * AKPAD + (c4 >> 1)] = make_uint2(l0, l1);
            *(uint4*)&Vs[r * AVPAD + c4] =
                make_uint4(f2tf(vv.x), f2tf(vv.y), f2tf(vv.z), f2tf(vv.w));
        }
        __syncthreads();

        // ---- S(16x64) = Q . K^T, bf16 3-term (4 k16-steps over DH=64) ----
        float S[8][4];
#pragma unroll
        for (int nf = 0; nf < 8; nf++)
#pragma unroll
            for (int i = 0; i < 4; i++) S[nf][i] = 0.f;

#pragma unroll
        for (int s = 0; s < 4; s++) {
            const int kb = s * 8;     // kpair base
            const int r0 = (qw + grp) * AQPAD;
            const int r1 = r0 + 8 * AQPAD;
            unsigned aH0 = QsH[r0 + kb + tig],     aH1 = QsH[r1 + kb + tig];
            unsigned aH2 = QsH[r0 + kb + tig + 4], aH3 = QsH[r1 + kb + tig + 4];
            unsigned aL0 = QsL[r0 + kb + tig],     aL1 = QsL[r1 + kb + tig];
            unsigned aL2 = QsL[r0 + kb + tig + 4], aL3 = QsL[r1 + kb + tig + 4];
#pragma unroll
            for (int nf = 0; nf < 8; nf++) {
                const int kr = (nf * 8 + grp) * AKPAD;
                unsigned bH0 = KsH[kr + kb + tig];
                unsigned bH1 = KsH[kr + kb + tig + 4];
                unsigned bL0 = KsL[kr + kb + tig];
                unsigned bL1 = KsL[kr + kb + tig + 4];
                mma16(S[nf], aH0, aH1, aH2, aH3, bH0, bH1);
                mma16(S[nf], aH0, aH1, aH2, aH3, bL0, bL1);
                mma16(S[nf], aL0, aL1, aL2, aL3, bH0, bH1);
            }
        }

        // ---- online softmax (rows qw+grp, qw+grp+8; 4 lanes/row) ----
        float mx0 = -1e30f, mx1 = -1e30f;
#pragma unroll
        for (int nf = 0; nf < 8; nf++) {
            mx0 = fmaxf(mx0, fmaxf(S[nf][0], S[nf][1]));
            mx1 = fmaxf(mx1, fmaxf(S[nf][2], S[nf][3]));
        }
        mx0 = fmaxf(mx0, __shfl_xor_sync(0xffffffffu, mx0, 1));
        mx0 = fmaxf(mx0, __shfl_xor_sync(0xffffffffu, mx0, 2));
        mx1 = fmaxf(mx1, __shfl_xor_sync(0xffffffffu, mx1, 1));
        mx1 = fmaxf(mx1, __shfl_xor_sync(0xffffffffu, mx1, 2));

        const float mn0 = fmaxf(m0, mx0);
        const float mn1 = fmaxf(m1, mx1);
        const float al0 = __expf(m0 - mn0);
        const float al1 = __expf(m1 - mn1);
        m0 = mn0; m1 = mn1;

        float rs0 = 0.f, rs1 = 0.f;
#pragma unroll
        for (int nf = 0; nf < 8; nf++) {
            float p0 = __expf(S[nf][0] - mn0);
            float p1 = __expf(S[nf][1] - mn0);
            float p2 = __expf(S[nf][2] - mn1);
            float p3 = __expf(S[nf][3] - mn1);
            rs0 += p0 + p1;
            rs1 += p2 + p3;
            const int cb = nf * 8 + 2 * tig;
            *(uint2*)&Ps[(qw + grp    ) * APPAD + cb] = make_uint2(f2tf(p0), f2tf(p1));
            *(uint2*)&Ps[(qw + grp + 8) * APPAD + cb] = make_uint2(f2tf(p2), f2tf(p3));
        }
        rs0 += __shfl_xor_sync(0xffffffffu, rs0, 1);
        rs0 += __shfl_xor_sync(0xffffffffu, rs0, 2);
        rs1 += __shfl_xor_sync(0xffffffffu, rs1, 1);
        rs1 += __shfl_xor_sync(0xffffffffu, rs1, 2);
        l0s = l0s * al0 + rs0;
        l1s = l1s * al1 + rs1;

#pragma unroll
        for (int nf = 0; nf < 8; nf++) {
            O[nf][0] *= al0; O[nf][1] *= al0;
            O[nf][2] *= al1; O[nf][3] *= al1;
        }
        __syncwarp();

        // ---- O(16x64) += P(16x64) . V(64x64), single tf32 ----
#pragma unroll
        for (int ks = 0; ks < 8; ks++) {
            const int kb = ks * 8;
            const int r0 = (qw + grp) * APPAD;
            const int r1 = r0 + 8 * APPAD;
            unsigned a0 = Ps[r0 + kb + tig],     a1 = Ps[r1 + kb + tig];
            unsigned a2 = Ps[r0 + kb + tig + 4], a3 = Ps[r1 + kb + tig + 4];
#pragma unroll
            for (int nf = 0; nf < 8; nf++) {
                unsigned b0 = Vs[(kb + tig    ) * AVPAD + nf * 8 + grp];
                unsigned b1 = Vs[(kb + tig + 4) * AVPAD + nf * 8 + grp];
                mma8(O[nf], a0, a1, a2, a3, b0, b1);
            }
        }
    }

    // ---- normalize + write ----
    const float inv0 = 1.f / l0s;
    const float inv1 = 1.f / l1s;
#pragma unroll
    for (int nf = 0; nf < 8; nf++) {
        const int c = coff + nf * 8 + 2 * tig;
        const size_t r0g = base + q0 + qw + grp;
        float2 o0 = make_float2(O[nf][0] * inv0, O[nf][1] * inv0);
        float2 o1 = make_float2(O[nf][2] * inv1, O[nf][3] * inv1);
        *(float2*)(g_AO + r0g * DIN + c)       = o0;
        *(float2*)(g_AO + (r0g + 8) * DIN + c) = o1;
    }
}

// ============================================================================
// launch
// ============================================================================
extern "C" void kernel_launch(void* const* d_in, const int* in_sizes, int n_in,
                              void* d_out, int out_size)
{
    (void)in_sizes; (void)n_in; (void)out_size;
    const float* q  = (const float*)d_in[0];
    const float* k  = (const float*)d_in[1];
    const float* v  = (const float*)d_in[2];
    const float* Wq = (const float*)d_in[3];
    const float* bq = (const float*)d_in[4];
    const float* Wk = (const float*)d_in[5];
    const float* bk = (const float*)d_in[6];
    const float* Wv = (const float*)d_in[7];
    const float* bv = (const float*)d_in[8];
    const float* Wo = (const float*)d_in[9];
    const float* bo = (const float*)d_in[10];
    float* out = (float*)d_out;

    cudaFuncSetAttribute(attn_bf16,
                         cudaFuncAttributeMaxDynamicSharedMemorySize, ATTN_SMEM);

    dim3 gg(DIN / 128, MROWS / 128);   // (8, 64)

    gemm_bf16<<<gg, 256, GSMEM>>>(q, Wq, bq, nullptr, 1, 0, 0);
    gemm_bf16<<<gg, 256, GSMEM>>>(k, Wk, bk, nullptr, 1, 0, 1);
    gemm_bf16<<<gg, 256, GSMEM>>>(v, Wv, bv, nullptr, 1, 0, 2);

    attn_bf16<<<dim3(SDIM / 128, BTOT * NH), 256, ATTN_SMEM>>>();

    gemm_bf16<<<gg, 256, GSMEM>>>(nullptr, Wo, bo, out, 0, 1, 3);
}